// round 2
// baseline (speedup 1.0000x reference)
#include <cuda_runtime.h>
#include <cuda_bf16.h>
#include <math.h>

// Problem constants
#define B_   2
#define S_   2048
#define H_   2048
#define NH_  16
#define NKV_ 4
#define HD_  128
#define BS_  (B_ * S_)          // 4096 token rows

// ---------------- scratch (device globals; no allocation allowed) ----------
__device__ float g_Q[BS_ * NH_ * HD_];    // [B,S,NH,HD]  (== [4096,2048])
__device__ float g_K[BS_ * NKV_ * HD_];   // [B,S,NKV,HD]
__device__ float g_V[BS_ * NKV_ * HD_];
__device__ float g_AO[BS_ * NH_ * HD_];   // attention output, [B,S,NH,HD]
__device__ float g_cos[BS_ * (HD_ / 2)];
__device__ float g_sin[BS_ * (HD_ / 2)];

// ---------------- RoPE table: cos/sin per (token, d<64) --------------------
__global__ void rope_table_kernel(const float* __restrict__ tvals,
                                  const float* __restrict__ rope_w,
                                  float* __restrict__ cosT,
                                  float* __restrict__ sinT) {
    int idx = blockIdx.x * blockDim.x + threadIdx.x;
    if (idx >= BS_ * 64) return;
    int pos = idx >> 6;
    int d   = idx & 63;
    // inv_freq = 10000^(-2d/128); compute in double for phase accuracy
    double invf = exp(-((double)(2 * d) / 128.0) * log(10000.0));
    double f = (double)tvals[pos] * invf * (double)rope_w[d];
    double sv, cv;
    sincos(f, &sv, &cv);
    cosT[idx] = (float)cv;
    sinT[idx] = (float)sv;
}

// ---------------- in-place RoPE apply on [BS, heads, 128] ------------------
__global__ void rope_apply_kernel(float* __restrict__ X,
                                  const float* __restrict__ cosT,
                                  const float* __restrict__ sinT,
                                  int heads) {
    int idx = blockIdx.x * blockDim.x + threadIdx.x;
    int total = BS_ * heads * 64;
    if (idx >= total) return;
    int d   = idx & 63;
    int h   = (idx >> 6) % heads;
    int pos = idx / (64 * heads);
    size_t base = ((size_t)pos * heads + h) * HD_;
    float c = cosT[pos * 64 + d];
    float s = sinT[pos * 64 + d];
    float x0 = X[base + d];
    float x1 = X[base + d + 64];
    X[base + d]      = x0 * c - x1 * s;
    X[base + d + 64] = x1 * c + x0 * s;
}

// ---------------- generic tiled fp32 GEMM: C = A[M,K] @ W[K,N] + bias ------
#define GBM 64
#define GBN 64
#define GBK 16

__global__ __launch_bounds__(256)
void gemm_kernel(const float* __restrict__ A, const float* __restrict__ W,
                 const float* __restrict__ bias, float* __restrict__ C,
                 int M, int N, int K) {
    __shared__ __align__(16) float As[GBK][GBM + 4];  // transposed, padded (68)
    __shared__ __align__(16) float Bs[GBK][GBN];

    int tid = threadIdx.x;
    int tx = tid & 15, ty = tid >> 4;
    int bm = blockIdx.y * GBM;
    int bn = blockIdx.x * GBN;

    float acc[4][4] = {};

    int arow = tid >> 2;             // 0..63
    int acol = (tid & 3) * 4;        // 0,4,8,12
    int brow = tid >> 4;             // 0..15
    int bcol = (tid & 15) * 4;       // 0..60

    const float* Ag = A + (size_t)(bm + arow) * K + acol;
    const float* Wg = W + (size_t)brow * N + bn + bcol;

    for (int k0 = 0; k0 < K; k0 += GBK) {
        float4 av = *(const float4*)(Ag + k0);
        float4 wv = *(const float4*)(Wg + (size_t)k0 * N);
        As[acol + 0][arow] = av.x;
        As[acol + 1][arow] = av.y;
        As[acol + 2][arow] = av.z;
        As[acol + 3][arow] = av.w;
        *(float4*)&Bs[brow][bcol] = wv;
        __syncthreads();
#pragma unroll
        for (int k = 0; k < GBK; k++) {
            float4 a = *(const float4*)&As[k][ty * 4];
            float4 b = *(const float4*)&Bs[k][tx * 4];
            float ar[4] = {a.x, a.y, a.z, a.w};
            float br[4] = {b.x, b.y, b.z, b.w};
#pragma unroll
            for (int i = 0; i < 4; i++)
#pragma unroll
                for (int j = 0; j < 4; j++)
                    acc[i][j] += ar[i] * br[j];
        }
        __syncthreads();
    }

    float bv[4] = {0.f, 0.f, 0.f, 0.f};
    if (bias) {
#pragma unroll
        for (int j = 0; j < 4; j++) bv[j] = bias[bn + tx * 4 + j];
    }
#pragma unroll
    for (int i = 0; i < 4; i++) {
        float4 o;
        o.x = acc[i][0] + bv[0];
        o.y = acc[i][1] + bv[1];
        o.z = acc[i][2] + bv[2];
        o.w = acc[i][3] + bv[3];
        *(float4*)&C[(size_t)(bm + ty * 4 + i) * N + bn + tx * 4] = o;
    }
}

// ---------------- flash attention (fp32, causal, GQA) ----------------------
#define AM 64          // q rows per block
#define AN 64          // keys per tile
#define AD 128         // head dim
#define KTP (AN + 4)   // Kt row stride (floats) - keeps 16B alignment
#define PSP (AN + 1)   // Ps row stride

__global__ __launch_bounds__(256)
void flash_attn_kernel(const float* __restrict__ Q, const float* __restrict__ K,
                       const float* __restrict__ V, float* __restrict__ AO) {
    extern __shared__ __align__(16) float smem[];
    float* Qs = smem;                       // AM*AD
    float* Kt = Qs + AM * AD;               // AD*KTP   (transposed K tile)
    float* Vs = Kt + AD * KTP;              // AN*AD
    float* Ps = Vs + AN * AD;               // AM*PSP

    int tid = threadIdx.x;
    int tx = tid & 15, ty = tid >> 4;
    int qt = blockIdx.x;          // q tile
    int h  = blockIdx.y;          // head
    int b  = blockIdx.z;          // batch
    int kvh = h >> 2;             // GQA: 4 heads per kv head

    const float scale = 0.08838834764831845f;  // 1/sqrt(128)

    // load Q tile
    for (int i = tid; i < AM * AD / 4; i += 256) {
        int r  = i >> 5;            // / (AD/4)
        int c4 = (i & 31) * 4;
        float4 v = *(const float4*)&Q[(((size_t)(b * S_ + qt * AM + r)) * NH_ + h) * AD + c4];
        *(float4*)&Qs[r * AD + c4] = v;
    }

    float o[4][8];
#pragma unroll
    for (int i = 0; i < 4; i++)
#pragma unroll
        for (int j = 0; j < 8; j++) o[i][j] = 0.f;
    float m[4] = {-1e30f, -1e30f, -1e30f, -1e30f};
    float l[4] = {0.f, 0.f, 0.f, 0.f};

    int nkt = qt + 1;   // causal: only tiles up to the diagonal
    for (int kt = 0; kt < nkt; kt++) {
        // load K tile transposed + V tile natural
        for (int i = tid; i < AN * AD / 4; i += 256) {
            int c  = i >> 5;
            int d4 = (i & 31) * 4;
            size_t grow = (((size_t)(b * S_ + kt * AN + c)) * NKV_ + kvh) * AD + d4;
            float4 kv = *(const float4*)&K[grow];
            Kt[(d4 + 0) * KTP + c] = kv.x;
            Kt[(d4 + 1) * KTP + c] = kv.y;
            Kt[(d4 + 2) * KTP + c] = kv.z;
            Kt[(d4 + 3) * KTP + c] = kv.w;
            float4 vv = *(const float4*)&V[grow];
            *(float4*)&Vs[c * AD + d4] = vv;
        }
        __syncthreads();

        // S = Q * K^T  (4x4 micro tile per thread)
        float sv[4][4] = {};
#pragma unroll 8
        for (int d = 0; d < AD; d++) {
            float4 kv = *(const float4*)&Kt[d * KTP + tx * 4];
            float kr[4] = {kv.x, kv.y, kv.z, kv.w};
            float qr[4];
#pragma unroll
            for (int i = 0; i < 4; i++) qr[i] = Qs[(ty * 4 + i) * AD + d];
#pragma unroll
            for (int i = 0; i < 4; i++)
#pragma unroll
                for (int j = 0; j < 4; j++)
                    sv[i][j] += qr[i] * kr[j];
        }

        // scale + causal mask (only diagonal tile needs it)
        if (kt == qt) {
#pragma unroll
            for (int i = 0; i < 4; i++)
#pragma unroll
                for (int j = 0; j < 4; j++) {
                    if (tx * 4 + j > ty * 4 + i) sv[i][j] = -1e30f;
                    else sv[i][j] *= scale;
                }
        } else {
#pragma unroll
            for (int i = 0; i < 4; i++)
#pragma unroll
                for (int j = 0; j < 4; j++) sv[i][j] *= scale;
        }

        // online softmax (row stats shared across the 16 tx lanes)
#pragma unroll
        for (int i = 0; i < 4; i++) {
            float tm = sv[i][0];
#pragma unroll
            for (int j = 1; j < 4; j++) tm = fmaxf(tm, sv[i][j]);
#pragma unroll
            for (int off = 1; off < 16; off <<= 1)
                tm = fmaxf(tm, __shfl_xor_sync(0xffffffffu, tm, off));
            float mn = fmaxf(m[i], tm);
            float alpha = expf(m[i] - mn);
            float rs = 0.f;
#pragma unroll
            for (int j = 0; j < 4; j++) {
                float p = expf(sv[i][j] - mn);
                sv[i][j] = p;
                rs += p;
            }
#pragma unroll
            for (int off = 1; off < 16; off <<= 1)
                rs += __shfl_xor_sync(0xffffffffu, rs, off);
            l[i] = l[i] * alpha + rs;
            m[i] = mn;
#pragma unroll
            for (int j = 0; j < 8; j++) o[i][j] *= alpha;
#pragma unroll
            for (int j = 0; j < 4; j++)
                Ps[(ty * 4 + i) * PSP + tx * 4 + j] = sv[i][j];
        }
        __syncthreads();

        // O += P * V
#pragma unroll 4
        for (int c = 0; c < AN; c++) {
            float4 v0 = *(const float4*)&Vs[c * AD + tx * 8];
            float4 v1 = *(const float4*)&Vs[c * AD + tx * 8 + 4];
#pragma unroll
            for (int i = 0; i < 4; i++) {
                float p = Ps[(ty * 4 + i) * PSP + c];
                o[i][0] += p * v0.x;
                o[i][1] += p * v0.y;
                o[i][2] += p * v0.z;
                o[i][3] += p * v0.w;
                o[i][4] += p * v1.x;
                o[i][5] += p * v1.y;
                o[i][6] += p * v1.z;
                o[i][7] += p * v1.w;
            }
        }
        __syncthreads();   // before next tile's smem writes
    }

    // epilogue: normalize, write AO[b, q, h, :]
#pragma unroll
    for (int i = 0; i < 4; i++) {
        float inv = 1.f / l[i];
        size_t base = (((size_t)(b * S_ + qt * AM + ty * 4 + i)) * NH_ + h) * AD + tx * 8;
        float4 w0, w1;
        w0.x = o[i][0] * inv; w0.y = o[i][1] * inv;
        w0.z = o[i][2] * inv; w0.w = o[i][3] * inv;
        w1.x = o[i][4] * inv; w1.y = o[i][5] * inv;
        w1.z = o[i][6] * inv; w1.w = o[i][7] * inv;
        *(float4*)&AO[base] = w0;
        *(float4*)&AO[base + 4] = w1;
    }
}

// ---------------- host launcher --------------------------------------------
extern "C" void kernel_launch(void* const* d_in, const int* in_sizes, int n_in,
                              void* d_out, int out_size) {
    const float* hidden = (const float*)d_in[0];
    const float* tvals  = (const float*)d_in[1];
    const float* wq = (const float*)d_in[2];
    const float* bq = (const float*)d_in[3];
    const float* wk = (const float*)d_in[4];
    const float* bk = (const float*)d_in[5];
    const float* wv = (const float*)d_in[6];
    const float* bv = (const float*)d_in[7];
    const float* wo = (const float*)d_in[8];
    const float* rw = (const float*)d_in[9];
    float* out = (float*)d_out;

    float *Qp, *Kp, *Vp, *AOp, *cosp, *sinp;
    cudaGetSymbolAddress((void**)&Qp,   g_Q);
    cudaGetSymbolAddress((void**)&Kp,   g_K);
    cudaGetSymbolAddress((void**)&Vp,   g_V);
    cudaGetSymbolAddress((void**)&AOp,  g_AO);
    cudaGetSymbolAddress((void**)&cosp, g_cos);
    cudaGetSymbolAddress((void**)&sinp, g_sin);

    // 1) RoPE cos/sin table
    {
        int n = BS_ * 64;
        rope_table_kernel<<<(n + 255) / 256, 256>>>(tvals, rw, cosp, sinp);
    }

    // 2) QKV projections
    gemm_kernel<<<dim3((NH_ * HD_) / GBN, BS_ / GBM), 256>>>(
        hidden, wq, bq, Qp, BS_, NH_ * HD_, H_);
    gemm_kernel<<<dim3((NKV_ * HD_) / GBN, BS_ / GBM), 256>>>(
        hidden, wk, bk, Kp, BS_, NKV_ * HD_, H_);
    gemm_kernel<<<dim3((NKV_ * HD_) / GBN, BS_ / GBM), 256>>>(
        hidden, wv, bv, Vp, BS_, NKV_ * HD_, H_);

    // 3) RoPE (Q and K)
    {
        int nq = BS_ * NH_ * 64;
        rope_apply_kernel<<<(nq + 255) / 256, 256>>>(Qp, cosp, sinp, NH_);
        int nk = BS_ * NKV_ * 64;
        rope_apply_kernel<<<(nk + 255) / 256, 256>>>(Kp, cosp, sinp, NKV_);
    }

    // 4) flash attention
    {
        size_t smem_bytes = (size_t)(AM * AD + AD * KTP + AN * AD + AM * PSP) * sizeof(float);
        cudaFuncSetAttribute(flash_attn_kernel,
                             cudaFuncAttributeMaxDynamicSharedMemorySize,
                             (int)smem_bytes);
        flash_attn_kernel<<<dim3(S_ / AM, NH_, B_), 256, smem_bytes>>>(Qp, Kp, Vp, AOp);
    }

    // 5) output projection -> d_out
    gemm_kernel<<<dim3(H_ / GBN, BS_ / GBM), 256>>>(
        AOp, wo, nullptr, out, BS_, H_, NH_ * HD_);
}

// round 6
// speedup vs baseline: 1.7614x; 1.7614x over previous
#include <cuda_runtime.h>
#include <cuda_bf16.h>
#include <math.h>
#include <stdint.h>

// Problem constants
#define B_   2
#define S_   2048
#define H_   2048
#define NH_  16
#define NKV_ 4
#define HD_  128
#define BS_  (B_ * S_)          // 4096 token rows

// ---------------- scratch (device globals; no allocation allowed) ----------
__device__ float g_Q[BS_ * NH_ * HD_];    // [B,S,NH,HD]  (== [4096,2048])
__device__ float g_K[BS_ * NKV_ * HD_];   // [B,S,NKV,HD]
__device__ float g_V[BS_ * NKV_ * HD_];
__device__ float g_AO[BS_ * NH_ * HD_];   // attention output, [B,S,NH,HD]
__device__ float g_cos[BS_ * (HD_ / 2)];
__device__ float g_sin[BS_ * (HD_ / 2)];

// ---------------- RoPE table: cos/sin per (token, d<64) --------------------
__global__ void rope_table_kernel(const float* __restrict__ tvals,
                                  const float* __restrict__ rope_w,
                                  float* __restrict__ cosT,
                                  float* __restrict__ sinT) {
    int idx = blockIdx.x * blockDim.x + threadIdx.x;
    if (idx >= BS_ * 64) return;
    int pos = idx >> 6;
    int d   = idx & 63;
    double invf = exp(-((double)(2 * d) / 128.0) * log(10000.0));
    double f = (double)tvals[pos] * invf * (double)rope_w[d];
    double sv, cv;
    sincos(f, &sv, &cv);
    cosT[idx] = (float)cv;
    sinT[idx] = (float)sv;
}

// ---------------- in-place RoPE apply on [BS, heads, 128] ------------------
__global__ void rope_apply_kernel(float* __restrict__ X,
                                  const float* __restrict__ cosT,
                                  const float* __restrict__ sinT,
                                  int heads) {
    int idx = blockIdx.x * blockDim.x + threadIdx.x;
    int total = BS_ * heads * 64;
    if (idx >= total) return;
    int d   = idx & 63;
    int h   = (idx >> 6) % heads;
    int pos = idx / (64 * heads);
    size_t base = ((size_t)pos * heads + h) * HD_;
    float c = cosT[pos * 64 + d];
    float s = sinT[pos * 64 + d];
    float x0 = X[base + d];
    float x1 = X[base + d + 64];
    X[base + d]      = x0 * c - x1 * s;
    X[base + d + 64] = x1 * c + x0 * s;
}

// ======================= tf32 tensor-core GEMM =============================
// C[M,N] = A[M,K] @ W[K,N] + bias ; fp32 in/out, tf32 mma, fp32 accumulate
#define BM 128
#define BN 128
#define BK 32
#define PA 36     // A smem row stride (floats): (4r+c)%32 distinct -> no conflicts
#define PB 136    // B smem row stride (floats): (8k+n)%32 distinct -> no conflicts

__device__ __forceinline__ void cp_async16(void* s, const void* g) {
    uint32_t sa = (uint32_t)__cvta_generic_to_shared(s);
    asm volatile("cp.async.cg.shared.global [%0], [%1], 16;\n" :: "r"(sa), "l"(g));
}
__device__ __forceinline__ uint32_t f2tf32(float x) {
    uint32_t r;
    asm("cvt.rna.tf32.f32 %0, %1;" : "=r"(r) : "f"(x));
    return r;
}
__device__ __forceinline__ void mma_tf32(float d[4], const uint32_t a[4], const uint32_t b[2]) {
    asm volatile(
        "mma.sync.aligned.m16n8k8.row.col.f32.tf32.tf32.f32 "
        "{%0,%1,%2,%3}, {%4,%5,%6,%7}, {%8,%9}, {%0,%1,%2,%3};\n"
        : "+f"(d[0]), "+f"(d[1]), "+f"(d[2]), "+f"(d[3])
        : "r"(a[0]), "r"(a[1]), "r"(a[2]), "r"(a[3]), "r"(b[0]), "r"(b[1]));
}

__global__ __launch_bounds__(256)
void gemm_tf32_kernel(const float* __restrict__ A, const float* __restrict__ W,
                      const float* __restrict__ bias, float* __restrict__ C,
                      int M, int N, int K) {
    extern __shared__ __align__(16) float smem[];
    float* As = smem;                    // 2 * BM * PA
    float* Bs = smem + 2 * BM * PA;      // 2 * BK * PB

    int tid  = threadIdx.x;
    int lane = tid & 31;
    int warp = tid >> 5;
    int wm = warp >> 2;       // 0..1  (64 rows each)
    int wn = warp & 3;        // 0..3  (32 cols each)
    int g  = lane >> 2;       // groupID   0..7
    int tg = lane & 3;        // thread-in-group 0..3
    int bm = blockIdx.y * BM;
    int bn = blockIdx.x * BN;

    float acc[4][4][4];
#pragma unroll
    for (int mt = 0; mt < 4; mt++)
#pragma unroll
        for (int nt = 0; nt < 4; nt++)
#pragma unroll
            for (int i = 0; i < 4; i++) acc[mt][nt][i] = 0.f;

    const int nk = K / BK;

    // ---- async tile loader: tile kt -> buffer buf ----
    // A tile: 128x32 floats = 1024 float4 ; B tile: 32x128 = 1024 float4
    auto issue_tile = [&](int kt, int buf) {
        const float* Ag = A + (size_t)bm * K + kt * BK;
        const float* Wg = W + (size_t)(kt * BK) * N + bn;
        float* Ad = As + buf * BM * PA;
        float* Bd = Bs + buf * BK * PB;
#pragma unroll
        for (int i = 0; i < 4; i++) {
            int li = tid + i * 256;
            int ar = li >> 3, ac = (li & 7) * 4;
            cp_async16(Ad + ar * PA + ac, Ag + (size_t)ar * K + ac);
            int br = li >> 5, bc = (li & 31) * 4;
            cp_async16(Bd + br * PB + bc, Wg + (size_t)br * N + bc);
        }
        asm volatile("cp.async.commit_group;\n");
    };

    issue_tile(0, 0);

    for (int kt = 0; kt < nk; kt++) {
        if (kt + 1 < nk) {
            issue_tile(kt + 1, (kt + 1) & 1);
            asm volatile("cp.async.wait_group 1;\n");
        } else {
            asm volatile("cp.async.wait_group 0;\n");
        }
        __syncthreads();

        const float* Ab = As + (kt & 1) * BM * PA + (wm * 64) * PA;
        const float* Bb = Bs + (kt & 1) * BK * PB + wn * 32;

#pragma unroll
        for (int ks = 0; ks < 4; ks++) {
            int k0 = ks * 8;
            uint32_t af[4][4];
            uint32_t bf[4][2];
#pragma unroll
            for (int mt = 0; mt < 4; mt++) {
                const float* p = Ab + (mt * 16 + g) * PA + k0 + tg;
                af[mt][0] = f2tf32(p[0]);
                af[mt][1] = f2tf32(p[8 * PA]);
                af[mt][2] = f2tf32(p[4]);
                af[mt][3] = f2tf32(p[8 * PA + 4]);
            }
#pragma unroll
            for (int nt = 0; nt < 4; nt++) {
                const float* p = Bb + (k0 + tg) * PB + nt * 8 + g;
                bf[nt][0] = f2tf32(p[0]);
                bf[nt][1] = f2tf32(p[4 * PB]);
            }
#pragma unroll
            for (int mt = 0; mt < 4; mt++)
#pragma unroll
                for (int nt = 0; nt < 4; nt++)
                    mma_tf32(acc[mt][nt], af[mt], bf[nt]);
        }
        __syncthreads();   // protect buffer being overwritten next iteration
    }

    // ---- epilogue ----
#pragma unroll
    for (int nt = 0; nt < 4; nt++) {
        int col = bn + wn * 32 + nt * 8 + tg * 2;
        float b0 = 0.f, b1 = 0.f;
        if (bias) { b0 = bias[col]; b1 = bias[col + 1]; }
#pragma unroll
        for (int mt = 0; mt < 4; mt++) {
            int row = bm + wm * 64 + mt * 16 + g;
            float2 v0 = make_float2(acc[mt][nt][0] + b0, acc[mt][nt][1] + b1);
            float2 v1 = make_float2(acc[mt][nt][2] + b0, acc[mt][nt][3] + b1);
            *(float2*)&C[(size_t)row * N + col] = v0;
            *(float2*)&C[(size_t)(row + 8) * N + col] = v1;
        }
    }
}

// ---------------- flash attention (fp32, causal, GQA) ----------------------
#define AM 64          // q rows per block
#define AN 64          // keys per tile
#define AD 128         // head dim
#define KTP (AN + 4)   // Kt row stride (floats)
#define PSP (AN + 1)   // Ps row stride

__global__ __launch_bounds__(256)
void flash_attn_kernel(const float* __restrict__ Q, const float* __restrict__ K,
                       const float* __restrict__ V, float* __restrict__ AO) {
    extern __shared__ __align__(16) float smem[];
    float* Qs = smem;                       // AM*AD
    float* Kt = Qs + AM * AD;               // AD*KTP
    float* Vs = Kt + AD * KTP;              // AN*AD
    float* Ps = Vs + AN * AD;               // AM*PSP

    int tid = threadIdx.x;
    int tx = tid & 15, ty = tid >> 4;
    int qt = blockIdx.x;
    int h  = blockIdx.y;
    int b  = blockIdx.z;
    int kvh = h >> 2;

    const float scale = 0.08838834764831845f;  // 1/sqrt(128)

    for (int i = tid; i < AM * AD / 4; i += 256) {
        int r  = i >> 5;
        int c4 = (i & 31) * 4;
        float4 v = *(const float4*)&Q[(((size_t)(b * S_ + qt * AM + r)) * NH_ + h) * AD + c4];
        *(float4*)&Qs[r * AD + c4] = v;
    }

    float o[4][8];
#pragma unroll
    for (int i = 0; i < 4; i++)
#pragma unroll
        for (int j = 0; j < 8; j++) o[i][j] = 0.f;
    float m[4] = {-1e30f, -1e30f, -1e30f, -1e30f};
    float l[4] = {0.f, 0.f, 0.f, 0.f};

    int nkt = qt + 1;
    for (int kt = 0; kt < nkt; kt++) {
        for (int i = tid; i < AN * AD / 4; i += 256) {
            int c  = i >> 5;
            int d4 = (i & 31) * 4;
            size_t grow = (((size_t)(b * S_ + kt * AN + c)) * NKV_ + kvh) * AD + d4;
            float4 kv = *(const float4*)&K[grow];
            Kt[(d4 + 0) * KTP + c] = kv.x;
            Kt[(d4 + 1) * KTP + c] = kv.y;
            Kt[(d4 + 2) * KTP + c] = kv.z;
            Kt[(d4 + 3) * KTP + c] = kv.w;
            float4 vv = *(const float4*)&V[grow];
            *(float4*)&Vs[c * AD + d4] = vv;
        }
        __syncthreads();

        float sv[4][4] = {};
#pragma unroll 8
        for (int d = 0; d < AD; d++) {
            float4 kv = *(const float4*)&Kt[d * KTP + tx * 4];
            float kr[4] = {kv.x, kv.y, kv.z, kv.w};
            float qr[4];
#pragma unroll
            for (int i = 0; i < 4; i++) qr[i] = Qs[(ty * 4 + i) * AD + d];
#pragma unroll
            for (int i = 0; i < 4; i++)
#pragma unroll
                for (int j = 0; j < 4; j++)
                    sv[i][j] += qr[i] * kr[j];
        }

        if (kt == qt) {
#pragma unroll
            for (int i = 0; i < 4; i++)
#pragma unroll
                for (int j = 0; j < 4; j++) {
                    if (tx * 4 + j > ty * 4 + i) sv[i][j] = -1e30f;
                    else sv[i][j] *= scale;
                }
        } else {
#pragma unroll
            for (int i = 0; i < 4; i++)
#pragma unroll
                for (int j = 0; j < 4; j++) sv[i][j] *= scale;
        }

#pragma unroll
        for (int i = 0; i < 4; i++) {
            float tm = sv[i][0];
#pragma unroll
            for (int j = 1; j < 4; j++) tm = fmaxf(tm, sv[i][j]);
#pragma unroll
            for (int off = 1; off < 16; off <<= 1)
                tm = fmaxf(tm, __shfl_xor_sync(0xffffffffu, tm, off));
            float mn = fmaxf(m[i], tm);
            float alpha = expf(m[i] - mn);
            float rs = 0.f;
#pragma unroll
            for (int j = 0; j < 4; j++) {
                float p = expf(sv[i][j] - mn);
                sv[i][j] = p;
                rs += p;
            }
#pragma unroll
            for (int off = 1; off < 16; off <<= 1)
                rs += __shfl_xor_sync(0xffffffffu, rs, off);
            l[i] = l[i] * alpha + rs;
            m[i] = mn;
#pragma unroll
            for (int j = 0; j < 8; j++) o[i][j] *= alpha;
#pragma unroll
            for (int j = 0; j < 4; j++)
                Ps[(ty * 4 + i) * PSP + tx * 4 + j] = sv[i][j];
        }
        __syncthreads();

#pragma unroll 4
        for (int c = 0; c < AN; c++) {
            float4 v0 = *(const float4*)&Vs[c * AD + tx * 8];
            float4 v1 = *(const float4*)&Vs[c * AD + tx * 8 + 4];
#pragma unroll
            for (int i = 0; i < 4; i++) {
                float p = Ps[(ty * 4 + i) * PSP + c];
                o[i][0] += p * v0.x;
                o[i][1] += p * v0.y;
                o[i][2] += p * v0.z;
                o[i][3] += p * v0.w;
                o[i][4] += p * v1.x;
                o[i][5] += p * v1.y;
                o[i][6] += p * v1.z;
                o[i][7] += p * v1.w;
            }
        }
        __syncthreads();
    }

#pragma unroll
    for (int i = 0; i < 4; i++) {
        float inv = 1.f / l[i];
        size_t base = (((size_t)(b * S_ + qt * AM + ty * 4 + i)) * NH_ + h) * AD + tx * 8;
        float4 w0, w1;
        w0.x = o[i][0] * inv; w0.y = o[i][1] * inv;
        w0.z = o[i][2] * inv; w0.w = o[i][3] * inv;
        w1.x = o[i][4] * inv; w1.y = o[i][5] * inv;
        w1.z = o[i][6] * inv; w1.w = o[i][7] * inv;
        *(float4*)&AO[base] = w0;
        *(float4*)&AO[base + 4] = w1;
    }
}

// ---------------- host launcher --------------------------------------------
extern "C" void kernel_launch(void* const* d_in, const int* in_sizes, int n_in,
                              void* d_out, int out_size) {
    const float* hidden = (const float*)d_in[0];
    const float* tvals  = (const float*)d_in[1];
    const float* wq = (const float*)d_in[2];
    const float* bq = (const float*)d_in[3];
    const float* wk = (const float*)d_in[4];
    const float* bk = (const float*)d_in[5];
    const float* wv = (const float*)d_in[6];
    const float* bv = (const float*)d_in[7];
    const float* wo = (const float*)d_in[8];
    const float* rw = (const float*)d_in[9];
    float* out = (float*)d_out;

    float *Qp, *Kp, *Vp, *AOp, *cosp, *sinp;
    cudaGetSymbolAddress((void**)&Qp,   g_Q);
    cudaGetSymbolAddress((void**)&Kp,   g_K);
    cudaGetSymbolAddress((void**)&Vp,   g_V);
    cudaGetSymbolAddress((void**)&AOp,  g_AO);
    cudaGetSymbolAddress((void**)&cosp, g_cos);
    cudaGetSymbolAddress((void**)&sinp, g_sin);

    // 1) RoPE cos/sin table
    {
        int n = BS_ * 64;
        rope_table_kernel<<<(n + 255) / 256, 256>>>(tvals, rw, cosp, sinp);
    }

    // 2) QKV projections (tf32 mma)
    size_t gsm = (size_t)(2 * BM * PA + 2 * BK * PB) * sizeof(float);  // ~70KB
    cudaFuncSetAttribute(gemm_tf32_kernel,
                         cudaFuncAttributeMaxDynamicSharedMemorySize, (int)gsm);
    gemm_tf32_kernel<<<dim3((NH_ * HD_) / BN, BS_ / BM), 256, gsm>>>(
        hidden, wq, bq, Qp, BS_, NH_ * HD_, H_);
    gemm_tf32_kernel<<<dim3((NKV_ * HD_) / BN, BS_ / BM), 256, gsm>>>(
        hidden, wk, bk, Kp, BS_, NKV_ * HD_, H_);
    gemm_tf32_kernel<<<dim3((NKV_ * HD_) / BN, BS_ / BM), 256, gsm>>>(
        hidden, wv, bv, Vp, BS_, NKV_ * HD_, H_);

    // 3) RoPE (Q and K)
    {
        int nq = BS_ * NH_ * 64;
        rope_apply_kernel<<<(nq + 255) / 256, 256>>>(Qp, cosp, sinp, NH_);
        int nk = BS_ * NKV_ * 64;
        rope_apply_kernel<<<(nk + 255) / 256, 256>>>(Kp, cosp, sinp, NKV_);
    }

    // 4) flash attention
    {
        size_t smem_bytes = (size_t)(AM * AD + AD * KTP + AN * AD + AM * PSP) * sizeof(float);
        cudaFuncSetAttribute(flash_attn_kernel,
                             cudaFuncAttributeMaxDynamicSharedMemorySize,
                             (int)smem_bytes);
        flash_attn_kernel<<<dim3(S_ / AM, NH_, B_), 256, smem_bytes>>>(Qp, Kp, Vp, AOp);
    }

    // 5) output projection -> d_out
    gemm_tf32_kernel<<<dim3(H_ / BN, BS_ / BM), 256, gsm>>>(
        AOp, wo, nullptr, out, BS_, H_, NH_ * HD_);
}

// round 7
// speedup vs baseline: 3.4613x; 1.9651x over previous
#include <cuda_runtime.h>
#include <cuda_bf16.h>
#include <math.h>
#include <stdint.h>

// Problem constants
#define B_   2
#define S_   2048
#define H_   2048
#define NH_  16
#define NKV_ 4
#define HD_  128
#define BS_  (B_ * S_)          // 4096 token rows

// ---------------- scratch (device globals; no allocation allowed) ----------
__device__ float g_Q[BS_ * NH_ * HD_];    // [B,S,NH,HD]
__device__ float g_K[BS_ * NKV_ * HD_];   // [B,S,NKV,HD]
__device__ float g_V[BS_ * NKV_ * HD_];
__device__ float g_AO[BS_ * NH_ * HD_];   // attention output
__device__ float g_cos[BS_ * (HD_ / 2)];
__device__ float g_sin[BS_ * (HD_ / 2)];

// ---------------- helpers ---------------------------------------------------
__device__ __forceinline__ void cp_async16(void* s, const void* g) {
    uint32_t sa = (uint32_t)__cvta_generic_to_shared(s);
    asm volatile("cp.async.cg.shared.global [%0], [%1], 16;\n" :: "r"(sa), "l"(g));
}
__device__ __forceinline__ uint32_t f2tf32(float x) {
    uint32_t r;
    asm("cvt.rna.tf32.f32 %0, %1;" : "=r"(r) : "f"(x));
    return r;
}
__device__ __forceinline__ float tf32rf(float x) {       // round value to tf32 grid
    return __uint_as_float(f2tf32(x));
}
__device__ __forceinline__ void mma_tf32(float d[4], const uint32_t a[4], const uint32_t b[2]) {
    asm volatile(
        "mma.sync.aligned.m16n8k8.row.col.f32.tf32.tf32.f32 "
        "{%0,%1,%2,%3}, {%4,%5,%6,%7}, {%8,%9}, {%0,%1,%2,%3};\n"
        : "+f"(d[0]), "+f"(d[1]), "+f"(d[2]), "+f"(d[3])
        : "r"(a[0]), "r"(a[1]), "r"(a[2]), "r"(a[3]), "r"(b[0]), "r"(b[1]));
}

// ---------------- RoPE table: cos/sin per (token, d<64) --------------------
__global__ void rope_table_kernel(const float* __restrict__ tvals,
                                  const float* __restrict__ rope_w,
                                  float* __restrict__ cosT,
                                  float* __restrict__ sinT) {
    int idx = blockIdx.x * blockDim.x + threadIdx.x;
    if (idx >= BS_ * 64) return;
    int pos = idx >> 6;
    int d   = idx & 63;
    double invf = exp(-((double)(2 * d) / 128.0) * log(10000.0));
    double f = (double)tvals[pos] * invf * (double)rope_w[d];
    double sv, cv;
    sincos(f, &sv, &cv);
    cosT[idx] = (float)cv;
    sinT[idx] = (float)sv;
}

// ---------------- in-place RoPE apply on [BS, heads, 128] ------------------
__global__ void rope_apply_kernel(float* __restrict__ X,
                                  const float* __restrict__ cosT,
                                  const float* __restrict__ sinT,
                                  int heads) {
    int idx = blockIdx.x * blockDim.x + threadIdx.x;
    int total = BS_ * heads * 64;
    if (idx >= total) return;
    int d   = idx & 63;
    int h   = (idx >> 6) % heads;
    int pos = idx / (64 * heads);
    size_t base = ((size_t)pos * heads + h) * HD_;
    float c = cosT[pos * 64 + d];
    float s = sinT[pos * 64 + d];
    float x0 = X[base + d];
    float x1 = X[base + d + 64];
    X[base + d]      = x0 * c - x1 * s;
    X[base + d + 64] = x1 * c + x0 * s;
}

// ======================= tf32 tensor-core GEMM =============================
#define BM 128
#define BN 128
#define BK 32
#define PA 36
#define PB 136

__global__ __launch_bounds__(256)
void gemm_tf32_kernel(const float* __restrict__ A, const float* __restrict__ W,
                      const float* __restrict__ bias, float* __restrict__ C,
                      int M, int N, int K) {
    extern __shared__ __align__(16) float smem[];
    float* As = smem;                    // 2 * BM * PA
    float* Bs = smem + 2 * BM * PA;      // 2 * BK * PB

    int tid  = threadIdx.x;
    int lane = tid & 31;
    int warp = tid >> 5;
    int wm = warp >> 2;
    int wn = warp & 3;
    int g  = lane >> 2;
    int tg = lane & 3;
    int bm = blockIdx.y * BM;
    int bn = blockIdx.x * BN;

    float acc[4][4][4];
#pragma unroll
    for (int mt = 0; mt < 4; mt++)
#pragma unroll
        for (int nt = 0; nt < 4; nt++)
#pragma unroll
            for (int i = 0; i < 4; i++) acc[mt][nt][i] = 0.f;

    const int nk = K / BK;

    auto issue_tile = [&](int kt, int buf) {
        const float* Ag = A + (size_t)bm * K + kt * BK;
        const float* Wg = W + (size_t)(kt * BK) * N + bn;
        float* Ad = As + buf * BM * PA;
        float* Bd = Bs + buf * BK * PB;
#pragma unroll
        for (int i = 0; i < 4; i++) {
            int li = tid + i * 256;
            int ar = li >> 3, ac = (li & 7) * 4;
            cp_async16(Ad + ar * PA + ac, Ag + (size_t)ar * K + ac);
            int br = li >> 5, bc = (li & 31) * 4;
            cp_async16(Bd + br * PB + bc, Wg + (size_t)br * N + bc);
        }
        asm volatile("cp.async.commit_group;\n");
    };

    issue_tile(0, 0);

    for (int kt = 0; kt < nk; kt++) {
        if (kt + 1 < nk) {
            issue_tile(kt + 1, (kt + 1) & 1);
            asm volatile("cp.async.wait_group 1;\n");
        } else {
            asm volatile("cp.async.wait_group 0;\n");
        }
        __syncthreads();

        const float* Ab = As + (kt & 1) * BM * PA + (wm * 64) * PA;
        const float* Bb = Bs + (kt & 1) * BK * PB + wn * 32;

#pragma unroll
        for (int ks = 0; ks < 4; ks++) {
            int k0 = ks * 8;
            uint32_t af[4][4];
            uint32_t bf[4][2];
#pragma unroll
            for (int mt = 0; mt < 4; mt++) {
                const float* p = Ab + (mt * 16 + g) * PA + k0 + tg;
                af[mt][0] = f2tf32(p[0]);
                af[mt][1] = f2tf32(p[8 * PA]);
                af[mt][2] = f2tf32(p[4]);
                af[mt][3] = f2tf32(p[8 * PA + 4]);
            }
#pragma unroll
            for (int nt = 0; nt < 4; nt++) {
                const float* p = Bb + (k0 + tg) * PB + nt * 8 + g;
                bf[nt][0] = f2tf32(p[0]);
                bf[nt][1] = f2tf32(p[4 * PB]);
            }
#pragma unroll
            for (int mt = 0; mt < 4; mt++)
#pragma unroll
                for (int nt = 0; nt < 4; nt++)
                    mma_tf32(acc[mt][nt], af[mt], bf[nt]);
        }
        __syncthreads();
    }

#pragma unroll
    for (int nt = 0; nt < 4; nt++) {
        int col = bn + wn * 32 + nt * 8 + tg * 2;
        float b0 = 0.f, b1 = 0.f;
        if (bias) { b0 = bias[col]; b1 = bias[col + 1]; }
#pragma unroll
        for (int mt = 0; mt < 4; mt++) {
            int row = bm + wm * 64 + mt * 16 + g;
            float2 v0 = make_float2(acc[mt][nt][0] + b0, acc[mt][nt][1] + b1);
            float2 v1 = make_float2(acc[mt][nt][2] + b0, acc[mt][nt][3] + b1);
            *(float2*)&C[(size_t)row * N + col] = v0;
            *(float2*)&C[(size_t)(row + 8) * N + col] = v1;
        }
    }
}

// ================= tf32 tensor-core flash attention ========================
// BQ=128 q rows per CTA (8 warps x 16 rows), BKV=64 keys per tile, HD=128.
#define FBQ 128
#define FBK 64
#define FLQ 132   // Qs row stride: (4m+k)%32 unique across fragment lanes
#define FLK 132   // Ks row stride
#define FLV 132   // Vs row stride
#define FLP 68    // Ps row stride

__global__ __launch_bounds__(256, 1)
void flash_tf32_kernel(const float* __restrict__ Q, const float* __restrict__ K,
                       const float* __restrict__ V, float* __restrict__ AO) {
    extern __shared__ __align__(16) float smem[];
    float* Qs = smem;                       // FBQ*FLQ
    float* Ps = Qs + FBQ * FLQ;             // FBQ*FLP
    float* Ks = Ps + FBQ * FLP;             // 2 * FBK*FLK
    float* Vs = Ks + 2 * FBK * FLK;         // FBK*FLV

    int tid = threadIdx.x;
    int lane = tid & 31;
    int w = tid >> 5;                 // 0..7
    int g = lane >> 2, tg = lane & 3;
    int qt = (int)(gridDim.x - 1) - (int)blockIdx.x;   // biggest work first
    int h = blockIdx.y, b = blockIdx.z;
    int kvh = h >> 2;

    const float scale = 0.08838834764831845f;  // 1/sqrt(128)

    // ---- async loaders for K/V tiles (64 x 128 floats) ----
    auto issue_K = [&](int kt, int buf) {
        const float* src = K + (((size_t)(b * S_ + kt * FBK)) * NKV_ + kvh) * HD_;
        float* dst = Ks + buf * FBK * FLK;
#pragma unroll
        for (int i = 0; i < 8; i++) {
            int li = tid + i * 256;
            int r = li >> 5, c = (li & 31) * 4;
            cp_async16(dst + r * FLK + c, src + (size_t)r * NKV_ * HD_ + c);
        }
        asm volatile("cp.async.commit_group;\n");
    };
    auto issue_V = [&](int kt) {
        const float* src = V + (((size_t)(b * S_ + kt * FBK)) * NKV_ + kvh) * HD_;
#pragma unroll
        for (int i = 0; i < 8; i++) {
            int li = tid + i * 256;
            int r = li >> 5, c = (li & 31) * 4;
            cp_async16(Vs + r * FLV + c, src + (size_t)r * NKV_ * HD_ + c);
        }
        asm volatile("cp.async.commit_group;\n");
    };

    int nkt = 2 * qt + 2;     // kv tiles needed (causal)

    issue_K(0, 0);
    issue_V(0);

    // ---- load Q tile: scale + round to tf32, store fp32 bits ----
    for (int i = tid; i < FBQ * HD_ / 4; i += 256) {
        int r = i >> 5, c4 = (i & 31) * 4;
        float4 v = *(const float4*)&Q[(((size_t)(b * S_ + qt * FBQ + r)) * NH_ + h) * HD_ + c4];
        Qs[r * FLQ + c4 + 0] = tf32rf(v.x * scale);
        Qs[r * FLQ + c4 + 1] = tf32rf(v.y * scale);
        Qs[r * FLQ + c4 + 2] = tf32rf(v.z * scale);
        Qs[r * FLQ + c4 + 3] = tf32rf(v.w * scale);
    }

    float oacc[16][4];
#pragma unroll
    for (int nt = 0; nt < 16; nt++)
#pragma unroll
        for (int i = 0; i < 4; i++) oacc[nt][i] = 0.f;
    float m0 = -1e30f, m1 = -1e30f;
    float l0 = 0.f, l1 = 0.f;

    int qrow_base = qt * FBQ + w * 16;

    for (int kt = 0; kt < nkt; kt++) {
        if (kt + 1 < nkt) {
            issue_K(kt + 1, (kt + 1) & 1);
            asm volatile("cp.async.wait_group 2;\n");
        } else {
            asm volatile("cp.async.wait_group 1;\n");
        }
        __syncthreads();   // K tile (and Qs on first iter) visible

        // ---- S = Q K^T  (per warp: 16 x 64) ----
        float sacc[8][4];
#pragma unroll
        for (int nt = 0; nt < 8; nt++)
#pragma unroll
            for (int i = 0; i < 4; i++) sacc[nt][i] = 0.f;

        const float* Kb = Ks + (kt & 1) * FBK * FLK;
        const float* Qw = Qs + (w * 16) * FLQ;

#pragma unroll
        for (int ks = 0; ks < 16; ks++) {
            int k0 = ks * 8;
            uint32_t af[4];
            const float* ap = Qw + g * FLQ + k0 + tg;
            af[0] = __float_as_uint(ap[0]);
            af[1] = __float_as_uint(ap[8 * FLQ]);
            af[2] = __float_as_uint(ap[4]);
            af[3] = __float_as_uint(ap[8 * FLQ + 4]);
#pragma unroll
            for (int nt = 0; nt < 8; nt++) {
                uint32_t bf[2];
                const float* bp = Kb + (nt * 8 + g) * FLK + k0 + tg;
                bf[0] = f2tf32(bp[0]);
                bf[1] = f2tf32(bp[4]);
                mma_tf32(sacc[nt], af, bf);
            }
        }

        // ---- causal mask (last two tiles only) ----
        if (kt >= 2 * qt) {
            int colb = kt * FBK;
#pragma unroll
            for (int nt = 0; nt < 8; nt++) {
                int c0 = colb + nt * 8 + tg * 2;
                if (c0 > qrow_base + g)          sacc[nt][0] = -1e30f;
                if (c0 + 1 > qrow_base + g)      sacc[nt][1] = -1e30f;
                if (c0 > qrow_base + g + 8)      sacc[nt][2] = -1e30f;
                if (c0 + 1 > qrow_base + g + 8)  sacc[nt][3] = -1e30f;
            }
        }

        // ---- online softmax (rows g and g+8; stats across tg lanes) ----
        float mx0 = -1e30f, mx1 = -1e30f;
#pragma unroll
        for (int nt = 0; nt < 8; nt++) {
            mx0 = fmaxf(mx0, fmaxf(sacc[nt][0], sacc[nt][1]));
            mx1 = fmaxf(mx1, fmaxf(sacc[nt][2], sacc[nt][3]));
        }
        mx0 = fmaxf(mx0, __shfl_xor_sync(0xffffffffu, mx0, 1));
        mx0 = fmaxf(mx0, __shfl_xor_sync(0xffffffffu, mx0, 2));
        mx1 = fmaxf(mx1, __shfl_xor_sync(0xffffffffu, mx1, 1));
        mx1 = fmaxf(mx1, __shfl_xor_sync(0xffffffffu, mx1, 2));
        float mn0 = fmaxf(m0, mx0);
        float mn1 = fmaxf(m1, mx1);
        float al0 = __expf(m0 - mn0);
        float al1 = __expf(m1 - mn1);
        m0 = mn0; m1 = mn1;
        float s0 = 0.f, s1 = 0.f;
        float* Pw = Ps + (w * 16) * FLP;
#pragma unroll
        for (int nt = 0; nt < 8; nt++) {
            float p0 = __expf(sacc[nt][0] - mn0);
            float p1 = __expf(sacc[nt][1] - mn0);
            float p2 = __expf(sacc[nt][2] - mn1);
            float p3 = __expf(sacc[nt][3] - mn1);
            s0 += p0 + p1;
            s1 += p2 + p3;
            int c = nt * 8 + tg * 2;
            Pw[g * FLP + c]           = tf32rf(p0);
            Pw[g * FLP + c + 1]       = tf32rf(p1);
            Pw[(g + 8) * FLP + c]     = tf32rf(p2);
            Pw[(g + 8) * FLP + c + 1] = tf32rf(p3);
        }
        s0 += __shfl_xor_sync(0xffffffffu, s0, 1);
        s0 += __shfl_xor_sync(0xffffffffu, s0, 2);
        s1 += __shfl_xor_sync(0xffffffffu, s1, 1);
        s1 += __shfl_xor_sync(0xffffffffu, s1, 2);
        l0 = l0 * al0 + s0;
        l1 = l1 * al1 + s1;
#pragma unroll
        for (int nt = 0; nt < 16; nt++) {
            oacc[nt][0] *= al0;
            oacc[nt][1] *= al0;
            oacc[nt][2] *= al1;
            oacc[nt][3] *= al1;
        }

        // ---- wait V tile ----
        if (kt + 1 < nkt) {
            asm volatile("cp.async.wait_group 1;\n");
        } else {
            asm volatile("cp.async.wait_group 0;\n");
        }
        __syncthreads();

        // ---- O += P V  (per warp: 16 x 128, K=64) ----
#pragma unroll
        for (int ks = 0; ks < 8; ks++) {
            int k0 = ks * 8;
            uint32_t af[4];
            const float* ap = Pw + g * FLP + k0 + tg;
            af[0] = __float_as_uint(ap[0]);
            af[1] = __float_as_uint(ap[8 * FLP]);
            af[2] = __float_as_uint(ap[4]);
            af[3] = __float_as_uint(ap[8 * FLP + 4]);
#pragma unroll
            for (int nt = 0; nt < 16; nt++) {
                uint32_t bf[2];
                const float* bp = Vs + (k0 + tg) * FLV + nt * 8 + g;
                bf[0] = f2tf32(bp[0]);
                bf[1] = f2tf32(bp[4 * FLV]);
                mma_tf32(oacc[nt], af, bf);
            }
        }
        __syncthreads();   // everyone done with Vs (and old K buffer)

        if (kt + 1 < nkt) issue_V(kt + 1);
    }

    // ---- epilogue: normalize + write AO[b, q, h, :] ----
    float rn0 = 1.f / l0;
    float rn1 = 1.f / l1;
    size_t r0 = (((size_t)(b * S_ + qrow_base + g)) * NH_ + h) * HD_;
    size_t r1 = (((size_t)(b * S_ + qrow_base + g + 8)) * NH_ + h) * HD_;
#pragma unroll
    for (int nt = 0; nt < 16; nt++) {
        int c = nt * 8 + tg * 2;
        *(float2*)&AO[r0 + c] = make_float2(oacc[nt][0] * rn0, oacc[nt][1] * rn0);
        *(float2*)&AO[r1 + c] = make_float2(oacc[nt][2] * rn1, oacc[nt][3] * rn1);
    }
}

// ---------------- host launcher --------------------------------------------
extern "C" void kernel_launch(void* const* d_in, const int* in_sizes, int n_in,
                              void* d_out, int out_size) {
    const float* hidden = (const float*)d_in[0];
    const float* tvals  = (const float*)d_in[1];
    const float* wq = (const float*)d_in[2];
    const float* bq = (const float*)d_in[3];
    const float* wk = (const float*)d_in[4];
    const float* bk = (const float*)d_in[5];
    const float* wv = (const float*)d_in[6];
    const float* bv = (const float*)d_in[7];
    const float* wo = (const float*)d_in[8];
    const float* rw = (const float*)d_in[9];
    float* out = (float*)d_out;

    float *Qp, *Kp, *Vp, *AOp, *cosp, *sinp;
    cudaGetSymbolAddress((void**)&Qp,   g_Q);
    cudaGetSymbolAddress((void**)&Kp,   g_K);
    cudaGetSymbolAddress((void**)&Vp,   g_V);
    cudaGetSymbolAddress((void**)&AOp,  g_AO);
    cudaGetSymbolAddress((void**)&cosp, g_cos);
    cudaGetSymbolAddress((void**)&sinp, g_sin);

    // 1) RoPE cos/sin table
    {
        int n = BS_ * 64;
        rope_table_kernel<<<(n + 255) / 256, 256>>>(tvals, rw, cosp, sinp);
    }

    // 2) QKV projections (tf32 mma)
    size_t gsm = (size_t)(2 * BM * PA + 2 * BK * PB) * sizeof(float);
    cudaFuncSetAttribute(gemm_tf32_kernel,
                         cudaFuncAttributeMaxDynamicSharedMemorySize, (int)gsm);
    gemm_tf32_kernel<<<dim3((NH_ * HD_) / BN, BS_ / BM), 256, gsm>>>(
        hidden, wq, bq, Qp, BS_, NH_ * HD_, H_);
    gemm_tf32_kernel<<<dim3((NKV_ * HD_) / BN, BS_ / BM), 256, gsm>>>(
        hidden, wk, bk, Kp, BS_, NKV_ * HD_, H_);
    gemm_tf32_kernel<<<dim3((NKV_ * HD_) / BN, BS_ / BM), 256, gsm>>>(
        hidden, wv, bv, Vp, BS_, NKV_ * HD_, H_);

    // 3) RoPE (Q and K)
    {
        int nq = BS_ * NH_ * 64;
        rope_apply_kernel<<<(nq + 255) / 256, 256>>>(Qp, cosp, sinp, NH_);
        int nk = BS_ * NKV_ * 64;
        rope_apply_kernel<<<(nk + 255) / 256, 256>>>(Kp, cosp, sinp, NKV_);
    }

    // 4) flash attention (tf32 tensor cores)
    {
        size_t fsm = (size_t)(FBQ * FLQ + FBQ * FLP + 2 * FBK * FLK + FBK * FLV) * sizeof(float);
        cudaFuncSetAttribute(flash_tf32_kernel,
                             cudaFuncAttributeMaxDynamicSharedMemorySize, (int)fsm);
        flash_tf32_kernel<<<dim3(S_ / FBQ, NH_, B_), 256, fsm>>>(Qp, Kp, Vp, AOp);
    }

    // 5) output projection -> d_out
    gemm_tf32_kernel<<<dim3(H_ / BN, BS_ / BM), 256, gsm>>>(
        AOp, wo, nullptr, out, BS_, H_, NH_ * HD_);
}

// round 12
// speedup vs baseline: 3.6548x; 1.0559x over previous
#include <cuda_runtime.h>
#include <cuda_bf16.h>
#include <math.h>
#include <stdint.h>

// Problem constants
#define B_   2
#define S_   2048
#define H_   2048
#define NH_  16
#define NKV_ 4
#define HD_  128
#define BS_  (B_ * S_)          // 4096 token rows

// ---------------- scratch (device globals; no allocation allowed) ----------
__device__ float g_Q[BS_ * NH_ * HD_];    // [B,S,NH,HD]
__device__ float g_K[BS_ * NKV_ * HD_];   // [B,S,NKV,HD]
__device__ float g_V[BS_ * NKV_ * HD_];
__device__ float g_AO[BS_ * NH_ * HD_];   // attention output (tf32-rounded)
__device__ float g_cos[BS_ * (HD_ / 2)];
__device__ float g_sin[BS_ * (HD_ / 2)];
// tf32-pre-rounded copies
__device__ float g_X [BS_ * H_];          // hidden, rounded
__device__ float g_Wq[H_ * (NH_ * HD_)];
__device__ float g_Wk[H_ * (NKV_ * HD_)];
__device__ float g_Wv[H_ * (NKV_ * HD_)];
__device__ float g_Wo[(NH_ * HD_) * H_];

// ---------------- helpers ---------------------------------------------------
__device__ __forceinline__ void cp_async16(void* s, const void* g) {
    uint32_t sa = (uint32_t)__cvta_generic_to_shared(s);
    asm volatile("cp.async.cg.shared.global [%0], [%1], 16;\n" :: "r"(sa), "l"(g));
}
__device__ __forceinline__ uint32_t f2tf32(float x) {
    uint32_t r;
    asm("cvt.rna.tf32.f32 %0, %1;" : "=r"(r) : "f"(x));
    return r;
}
__device__ __forceinline__ float tf32rf(float x) {       // round value to tf32 grid
    return __uint_as_float(f2tf32(x));
}
__device__ __forceinline__ void mma_tf32(float d[4], const uint32_t a[4], const uint32_t b[2]) {
    asm volatile(
        "mma.sync.aligned.m16n8k8.row.col.f32.tf32.tf32.f32 "
        "{%0,%1,%2,%3}, {%4,%5,%6,%7}, {%8,%9}, {%0,%1,%2,%3};\n"
        : "+f"(d[0]), "+f"(d[1]), "+f"(d[2]), "+f"(d[3])
        : "r"(a[0]), "r"(a[1]), "r"(a[2]), "r"(a[3]), "r"(b[0]), "r"(b[1]));
}

// ---------------- elementwise tf32 pre-round -------------------------------
__global__ void round_tf32_kernel(const float* __restrict__ in,
                                  float* __restrict__ out, int n4) {
    int i = blockIdx.x * blockDim.x + threadIdx.x;
    if (i >= n4) return;
    float4 v = ((const float4*)in)[i];
    v.x = tf32rf(v.x); v.y = tf32rf(v.y); v.z = tf32rf(v.z); v.w = tf32rf(v.w);
    ((float4*)out)[i] = v;
}

// ---------------- RoPE table: cos/sin per (token, d<64) --------------------
__global__ void rope_table_kernel(const float* __restrict__ tvals,
                                  const float* __restrict__ rope_w,
                                  float* __restrict__ cosT,
                                  float* __restrict__ sinT) {
    int idx = blockIdx.x * blockDim.x + threadIdx.x;
    if (idx >= BS_ * 64) return;
    int pos = idx >> 6;
    int d   = idx & 63;
    double invf = exp(-((double)(2 * d) / 128.0) * log(10000.0));
    double f = (double)tvals[pos] * invf * (double)rope_w[d];
    double sv, cv;
    sincos(f, &sv, &cv);
    cosT[idx] = (float)cv;
    sinT[idx] = (float)sv;
}

// -------- in-place RoPE apply on [BS, heads, 128]; optional tf32 round -----
__global__ void rope_apply_kernel(float* __restrict__ X,
                                  const float* __restrict__ cosT,
                                  const float* __restrict__ sinT,
                                  int heads, int do_round) {
    int idx = blockIdx.x * blockDim.x + threadIdx.x;
    int total = BS_ * heads * 64;
    if (idx >= total) return;
    int d   = idx & 63;
    int h   = (idx >> 6) % heads;
    int pos = idx / (64 * heads);
    size_t base = ((size_t)pos * heads + h) * HD_;
    float c = cosT[pos * 64 + d];
    float s = sinT[pos * 64 + d];
    float x0 = X[base + d];
    float x1 = X[base + d + 64];
    float y0 = x0 * c - x1 * s;
    float y1 = x1 * c + x0 * s;
    if (do_round) { y0 = tf32rf(y0); y1 = tf32rf(y1); }
    X[base + d]      = y0;
    X[base + d + 64] = y1;
}

// ======================= tf32 tensor-core GEMM core ========================
// Inputs assumed PRE-ROUNDED to tf32 grid. No cvt in the mainloop.
#define BM 128
#define BN 128
#define BK 32
#define PA 36
#define PB 136
#define GEMM_SMEM ((2 * BM * PA + 2 * BK * PB) * 4)

// Computes one 128x128 C tile: acc = A[bm:,:K] @ W[:, bn:]; writes via cb.
template <typename EpFn>
__device__ __forceinline__ void gemm_tile_body(
    const float* __restrict__ A, const float* __restrict__ W,
    int bm, int bn, int K, int N, float* smem, EpFn epilogue) {
    float* As = smem;                    // 2 * BM * PA
    float* Bs = smem + 2 * BM * PA;      // 2 * BK * PB

    int tid  = threadIdx.x;
    int lane = tid & 31;
    int warp = tid >> 5;
    int wm = warp >> 2;
    int wn = warp & 3;
    int g  = lane >> 2;
    int tg = lane & 3;

    float acc[4][4][4];
#pragma unroll
    for (int mt = 0; mt < 4; mt++)
#pragma unroll
        for (int nt = 0; nt < 4; nt++)
#pragma unroll
            for (int i = 0; i < 4; i++) acc[mt][nt][i] = 0.f;

    const int nk = K / BK;

    auto issue_tile = [&](int kt, int buf) {
        const float* Ag = A + (size_t)bm * K + kt * BK;
        const float* Wg = W + (size_t)(kt * BK) * N + bn;
        float* Ad = As + buf * BM * PA;
        float* Bd = Bs + buf * BK * PB;
#pragma unroll
        for (int i = 0; i < 4; i++) {
            int li = tid + i * 256;
            int ar = li >> 3, ac = (li & 7) * 4;
            cp_async16(Ad + ar * PA + ac, Ag + (size_t)ar * K + ac);
            int br = li >> 5, bc = (li & 31) * 4;
            cp_async16(Bd + br * PB + bc, Wg + (size_t)br * N + bc);
        }
        asm volatile("cp.async.commit_group;\n");
    };

    issue_tile(0, 0);

    for (int kt = 0; kt < nk; kt++) {
        if (kt + 1 < nk) {
            issue_tile(kt + 1, (kt + 1) & 1);
            asm volatile("cp.async.wait_group 1;\n");
        } else {
            asm volatile("cp.async.wait_group 0;\n");
        }
        __syncthreads();

        const float* Ab = As + (kt & 1) * BM * PA + (wm * 64) * PA;
        const float* Bb = Bs + (kt & 1) * BK * PB + wn * 32;

#pragma unroll
        for (int ks = 0; ks < 4; ks++) {
            int k0 = ks * 8;
            uint32_t af[4][4];
            uint32_t bf[4][2];
#pragma unroll
            for (int mt = 0; mt < 4; mt++) {
                const float* p = Ab + (mt * 16 + g) * PA + k0 + tg;
                af[mt][0] = __float_as_uint(p[0]);
                af[mt][1] = __float_as_uint(p[8 * PA]);
                af[mt][2] = __float_as_uint(p[4]);
                af[mt][3] = __float_as_uint(p[8 * PA + 4]);
            }
#pragma unroll
            for (int nt = 0; nt < 4; nt++) {
                const float* p = Bb + (k0 + tg) * PB + nt * 8 + g;
                bf[nt][0] = __float_as_uint(p[0]);
                bf[nt][1] = __float_as_uint(p[4 * PB]);
            }
#pragma unroll
            for (int mt = 0; mt < 4; mt++)
#pragma unroll
                for (int nt = 0; nt < 4; nt++)
                    mma_tf32(acc[mt][nt], af[mt], bf[nt]);
        }
        __syncthreads();
    }

    // epilogue callback: (mt, nt, local col pair index, values)
#pragma unroll
    for (int nt = 0; nt < 4; nt++) {
#pragma unroll
        for (int mt = 0; mt < 4; mt++) {
            int row = wm * 64 + mt * 16 + g;          // local row in tile
            int col = wn * 32 + nt * 8 + tg * 2;      // local col in tile
            epilogue(row, col, acc[mt][nt]);
        }
    }
}

// ---- fused QKV projection: grid.x in [0,24) tiles over concat N=3072 ------
__global__ __launch_bounds__(256, 2)
void qkv_gemm_kernel(const float* __restrict__ X,
                     const float* __restrict__ Wq, const float* __restrict__ Wk,
                     const float* __restrict__ Wv,
                     const float* __restrict__ bq, const float* __restrict__ bk,
                     const float* __restrict__ bv,
                     float* __restrict__ Qo, float* __restrict__ Ko,
                     float* __restrict__ Vo) {
    extern __shared__ __align__(16) float smem[];
    int ct = blockIdx.x;
    int bm = blockIdx.y * BM;

    const float* W; const float* bias; float* C;
    int N, bn; bool roundV = false;
    if (ct < 16)      { W = Wq; bias = bq; C = Qo; N = 2048; bn = ct * BN; }
    else if (ct < 20) { W = Wk; bias = bk; C = Ko; N = 512;  bn = (ct - 16) * BN; }
    else              { W = Wv; bias = bv; C = Vo; N = 512;  bn = (ct - 20) * BN; roundV = true; }

    gemm_tile_body(X, W, bm, bn, H_, N, smem,
        [&](int r, int c, const float* v) {
            int row = bm + r;
            int col = bn + c;
            float b0 = bias[col], b1 = bias[col + 1];
            float x0 = v[0] + b0, x1 = v[1] + b1;
            float y0 = v[2] + b0, y1 = v[3] + b1;
            if (roundV) { x0 = tf32rf(x0); x1 = tf32rf(x1); y0 = tf32rf(y0); y1 = tf32rf(y1); }
            *(float2*)&C[(size_t)row * N + col] = make_float2(x0, x1);
            *(float2*)&C[(size_t)(row + 8) * N + col] = make_float2(y0, y1);
        });
}

// ---- plain GEMM (for output projection) -----------------------------------
__global__ __launch_bounds__(256, 2)
void gemm_tf32_kernel(const float* __restrict__ A, const float* __restrict__ W,
                      float* __restrict__ C, int M, int N, int K) {
    extern __shared__ __align__(16) float smem[];
    int bm = blockIdx.y * BM;
    int bn = blockIdx.x * BN;
    gemm_tile_body(A, W, bm, bn, K, N, smem,
        [&](int r, int c, const float* v) {
            int row = bm + r;
            int col = bn + c;
            *(float2*)&C[(size_t)row * N + col] = make_float2(v[0], v[1]);
            *(float2*)&C[(size_t)(row + 8) * N + col] = make_float2(v[2], v[3]);
        });
}

// ================= tf32 tensor-core flash attention ========================
#define FBQ 128
#define FBK 64
#define FLQ 132
#define FLK 132
#define FLV 132
#define FLP 68

__global__ __launch_bounds__(256, 1)
void flash_tf32_kernel(const float* __restrict__ Q, const float* __restrict__ K,
                       const float* __restrict__ V, float* __restrict__ AO) {
    extern __shared__ __align__(16) float smem[];
    float* Qs = smem;                       // FBQ*FLQ
    float* Ps = Qs + FBQ * FLQ;             // FBQ*FLP
    float* Ks = Ps + FBQ * FLP;             // 2 * FBK*FLK
    float* Vs = Ks + 2 * FBK * FLK;         // FBK*FLV

    int tid = threadIdx.x;
    int lane = tid & 31;
    int w = tid >> 5;
    int g = lane >> 2, tg = lane & 3;
    int qt = (int)(gridDim.x - 1) - (int)blockIdx.x;
    int h = blockIdx.y, b = blockIdx.z;
    int kvh = h >> 2;

    const float scale = 0.08838834764831845f;  // 1/sqrt(128)

    auto issue_K = [&](int kt, int buf) {
        const float* src = K + (((size_t)(b * S_ + kt * FBK)) * NKV_ + kvh) * HD_;
        float* dst = Ks + buf * FBK * FLK;
#pragma unroll
        for (int i = 0; i < 8; i++) {
            int li = tid + i * 256;
            int r = li >> 5, c = (li & 31) * 4;
            cp_async16(dst + r * FLK + c, src + (size_t)r * NKV_ * HD_ + c);
        }
        asm volatile("cp.async.commit_group;\n");
    };
    auto issue_V = [&](int kt) {
        const float* src = V + (((size_t)(b * S_ + kt * FBK)) * NKV_ + kvh) * HD_;
#pragma unroll
        for (int i = 0; i < 8; i++) {
            int li = tid + i * 256;
            int r = li >> 5, c = (li & 31) * 4;
            cp_async16(Vs + r * FLV + c, src + (size_t)r * NKV_ * HD_ + c);
        }
        asm volatile("cp.async.commit_group;\n");
    };

    int nkt = 2 * qt + 2;

    issue_K(0, 0);
    issue_V(0);

    // Q tile: scale + round to tf32
    for (int i = tid; i < FBQ * HD_ / 4; i += 256) {
        int r = i >> 5, c4 = (i & 31) * 4;
        float4 v = *(const float4*)&Q[(((size_t)(b * S_ + qt * FBQ + r)) * NH_ + h) * HD_ + c4];
        Qs[r * FLQ + c4 + 0] = tf32rf(v.x * scale);
        Qs[r * FLQ + c4 + 1] = tf32rf(v.y * scale);
        Qs[r * FLQ + c4 + 2] = tf32rf(v.z * scale);
        Qs[r * FLQ + c4 + 3] = tf32rf(v.w * scale);
    }

    float oacc[16][4];
#pragma unroll
    for (int nt = 0; nt < 16; nt++)
#pragma unroll
        for (int i = 0; i < 4; i++) oacc[nt][i] = 0.f;
    float m0 = -1e30f, m1 = -1e30f;
    float l0 = 0.f, l1 = 0.f;

    int qrow_base = qt * FBQ + w * 16;

    for (int kt = 0; kt < nkt; kt++) {
        if (kt + 1 < nkt) {
            issue_K(kt + 1, (kt + 1) & 1);
            asm volatile("cp.async.wait_group 2;\n");
        } else {
            asm volatile("cp.async.wait_group 1;\n");
        }
        __syncthreads();

        float sacc[8][4];
#pragma unroll
        for (int nt = 0; nt < 8; nt++)
#pragma unroll
            for (int i = 0; i < 4; i++) sacc[nt][i] = 0.f;

        const float* Kb = Ks + (kt & 1) * FBK * FLK;
        const float* Qw = Qs + (w * 16) * FLQ;

#pragma unroll
        for (int ks = 0; ks < 16; ks++) {
            int k0 = ks * 8;
            uint32_t af[4];
            const float* ap = Qw + g * FLQ + k0 + tg;
            af[0] = __float_as_uint(ap[0]);
            af[1] = __float_as_uint(ap[8 * FLQ]);
            af[2] = __float_as_uint(ap[4]);
            af[3] = __float_as_uint(ap[8 * FLQ + 4]);
#pragma unroll
            for (int nt = 0; nt < 8; nt++) {
                uint32_t bf[2];
                const float* bp = Kb + (nt * 8 + g) * FLK + k0 + tg;
                bf[0] = __float_as_uint(bp[0]);
                bf[1] = __float_as_uint(bp[4]);
                mma_tf32(sacc[nt], af, bf);
            }
        }

        if (kt >= 2 * qt) {
            int colb = kt * FBK;
#pragma unroll
            for (int nt = 0; nt < 8; nt++) {
                int c0 = colb + nt * 8 + tg * 2;
                if (c0 > qrow_base + g)          sacc[nt][0] = -1e30f;
                if (c0 + 1 > qrow_base + g)      sacc[nt][1] = -1e30f;
                if (c0 > qrow_base + g + 8)      sacc[nt][2] = -1e30f;
                if (c0 + 1 > qrow_base + g + 8)  sacc[nt][3] = -1e30f;
            }
        }

        float mx0 = -1e30f, mx1 = -1e30f;
#pragma unroll
        for (int nt = 0; nt < 8; nt++) {
            mx0 = fmaxf(mx0, fmaxf(sacc[nt][0], sacc[nt][1]));
            mx1 = fmaxf(mx1, fmaxf(sacc[nt][2], sacc[nt][3]));
        }
        mx0 = fmaxf(mx0, __shfl_xor_sync(0xffffffffu, mx0, 1));
        mx0 = fmaxf(mx0, __shfl_xor_sync(0xffffffffu, mx0, 2));
        mx1 = fmaxf(mx1, __shfl_xor_sync(0xffffffffu, mx1, 1));
        mx1 = fmaxf(mx1, __shfl_xor_sync(0xffffffffu, mx1, 2));
        float mn0 = fmaxf(m0, mx0);
        float mn1 = fmaxf(m1, mx1);
        float al0 = __expf(m0 - mn0);
        float al1 = __expf(m1 - mn1);
        m0 = mn0; m1 = mn1;
        float s0 = 0.f, s1 = 0.f;
        float* Pw = Ps + (w * 16) * FLP;
#pragma unroll
        for (int nt = 0; nt < 8; nt++) {
            float p0 = __expf(sacc[nt][0] - mn0);
            float p1 = __expf(sacc[nt][1] - mn0);
            float p2 = __expf(sacc[nt][2] - mn1);
            float p3 = __expf(sacc[nt][3] - mn1);
            s0 += p0 + p1;
            s1 += p2 + p3;
            int c = nt * 8 + tg * 2;
            Pw[g * FLP + c]           = tf32rf(p0);
            Pw[g * FLP + c + 1]       = tf32rf(p1);
            Pw[(g + 8) * FLP + c]     = tf32rf(p2);
            Pw[(g + 8) * FLP + c + 1] = tf32rf(p3);
        }
        s0 += __shfl_xor_sync(0xffffffffu, s0, 1);
        s0 += __shfl_xor_sync(0xffffffffu, s0, 2);
        s1 += __shfl_xor_sync(0xffffffffu, s1, 1);
        s1 += __shfl_xor_sync(0xffffffffu, s1, 2);
        l0 = l0 * al0 + s0;
        l1 = l1 * al1 + s1;
#pragma unroll
        for (int nt = 0; nt < 16; nt++) {
            oacc[nt][0] *= al0;
            oacc[nt][1] *= al0;
            oacc[nt][2] *= al1;
            oacc[nt][3] *= al1;
        }

        if (kt + 1 < nkt) {
            asm volatile("cp.async.wait_group 1;\n");
        } else {
            asm volatile("cp.async.wait_group 0;\n");
        }
        __syncthreads();

#pragma unroll
        for (int ks = 0; ks < 8; ks++) {
            int k0 = ks * 8;
            uint32_t af[4];
            const float* ap = Pw + g * FLP + k0 + tg;
            af[0] = __float_as_uint(ap[0]);
            af[1] = __float_as_uint(ap[8 * FLP]);
            af[2] = __float_as_uint(ap[4]);
            af[3] = __float_as_uint(ap[8 * FLP + 4]);
#pragma unroll
            for (int nt = 0; nt < 16; nt++) {
                uint32_t bf[2];
                const float* bp = Vs + (k0 + tg) * FLV + nt * 8 + g;
                bf[0] = __float_as_uint(bp[0]);
                bf[1] = __float_as_uint(bp[4 * FLV]);
                mma_tf32(oacc[nt], af, bf);
            }
        }
        __syncthreads();

        if (kt + 1 < nkt) issue_V(kt + 1);
    }

    // epilogue: normalize + round to tf32 (AO feeds O-proj) + write
    float rn0 = 1.f / l0;
    float rn1 = 1.f / l1;
    size_t r0 = (((size_t)(b * S_ + qrow_base + g)) * NH_ + h) * HD_;
    size_t r1 = (((size_t)(b * S_ + qrow_base + g + 8)) * NH_ + h) * HD_;
#pragma unroll
    for (int nt = 0; nt < 16; nt++) {
        int c = nt * 8 + tg * 2;
        *(float2*)&AO[r0 + c] = make_float2(tf32rf(oacc[nt][0] * rn0), tf32rf(oacc[nt][1] * rn0));
        *(float2*)&AO[r1 + c] = make_float2(tf32rf(oacc[nt][2] * rn1), tf32rf(oacc[nt][3] * rn1));
    }
}

// ---------------- host launcher --------------------------------------------
extern "C" void kernel_launch(void* const* d_in, const int* in_sizes, int n_in,
                              void* d_out, int out_size) {
    const float* hidden = (const float*)d_in[0];
    const float* tvals  = (const float*)d_in[1];
    const float* wq = (const float*)d_in[2];
    const float* bq = (const float*)d_in[3];
    const float* wk = (const float*)d_in[4];
    const float* bk = (const float*)d_in[5];
    const float* wv = (const float*)d_in[6];
    const float* bv = (const float*)d_in[7];
    const float* wo = (const float*)d_in[8];
    const float* rw = (const float*)d_in[9];
    float* out = (float*)d_out;

    float *Qp, *Kp, *Vp, *AOp, *cosp, *sinp;
    float *Xp, *Wqp, *Wkp, *Wvp, *Wop;
    cudaGetSymbolAddress((void**)&Qp,   g_Q);
    cudaGetSymbolAddress((void**)&Kp,   g_K);
    cudaGetSymbolAddress((void**)&Vp,   g_V);
    cudaGetSymbolAddress((void**)&AOp,  g_AO);
    cudaGetSymbolAddress((void**)&cosp, g_cos);
    cudaGetSymbolAddress((void**)&sinp, g_sin);
    cudaGetSymbolAddress((void**)&Xp,   g_X);
    cudaGetSymbolAddress((void**)&Wqp,  g_Wq);
    cudaGetSymbolAddress((void**)&Wkp,  g_Wk);
    cudaGetSymbolAddress((void**)&Wvp,  g_Wv);
    cudaGetSymbolAddress((void**)&Wop,  g_Wo);

    // 0) tf32 pre-round: hidden + weights
    {
        int n;
        n = BS_ * H_ / 4;
        round_tf32_kernel<<<(n + 255) / 256, 256>>>(hidden, Xp, n);
        n = H_ * NH_ * HD_ / 4;
        round_tf32_kernel<<<(n + 255) / 256, 256>>>(wq, Wqp, n);
        n = H_ * NKV_ * HD_ / 4;
        round_tf32_kernel<<<(n + 255) / 256, 256>>>(wk, Wkp, n);
        round_tf32_kernel<<<(n + 255) / 256, 256>>>(wv, Wvp, n);
        n = NH_ * HD_ * H_ / 4;
        round_tf32_kernel<<<(n + 255) / 256, 256>>>(wo, Wop, n);
    }

    // 1) RoPE cos/sin table
    {
        int n = BS_ * 64;
        rope_table_kernel<<<(n + 255) / 256, 256>>>(tvals, rw, cosp, sinp);
    }

    // 2) fused QKV projection
    cudaFuncSetAttribute(qkv_gemm_kernel,
                         cudaFuncAttributeMaxDynamicSharedMemorySize, GEMM_SMEM);
    qkv_gemm_kernel<<<dim3(24, BS_ / BM), 256, GEMM_SMEM>>>(
        Xp, Wqp, Wkp, Wvp, bq, bk, bv, Qp, Kp, Vp);

    // 3) RoPE (Q plain; K rounded to tf32 for flash)
    {
        int nq = BS_ * NH_ * 64;
        rope_apply_kernel<<<(nq + 255) / 256, 256>>>(Qp, cosp, sinp, NH_, 0);
        int nk = BS_ * NKV_ * 64;
        rope_apply_kernel<<<(nk + 255) / 256, 256>>>(Kp, cosp, sinp, NKV_, 1);
    }

    // 4) flash attention (tf32 tensor cores)
    {
        size_t fsm = (size_t)(FBQ * FLQ + FBQ * FLP + 2 * FBK * FLK + FBK * FLV) * sizeof(float);
        cudaFuncSetAttribute(flash_tf32_kernel,
                             cudaFuncAttributeMaxDynamicSharedMemorySize, (int)fsm);
        flash_tf32_kernel<<<dim3(S_ / FBQ, NH_, B_), 256, fsm>>>(Qp, Kp, Vp, AOp);
    }

    // 5) output projection -> d_out
    cudaFuncSetAttribute(gemm_tf32_kernel,
                         cudaFuncAttributeMaxDynamicSharedMemorySize, GEMM_SMEM);
    gemm_tf32_kernel<<<dim3(H_ / BN, BS_ / BM), 256, GEMM_SMEM>>>(
        AOp, Wop, out, BS_, H_, NH_ * HD_);
}